// round 10
// baseline (speedup 1.0000x reference)
#include <cuda_runtime.h>
#include <cuda_bf16.h>
#include <math.h>

typedef unsigned int u32;

#define Bt 8
#define Nn 4096
#define Dd 1024
#define Pp 16
#define ITERS 3
#define TN 128
#define DK 128
#define NT (Nn/TN)
#define XSTRIDE (DK+4)
#define LOG2PI 1.8378770664093453f

// smem: xs (M-step tile) then qs
#define O_QS   (TN*XSTRIDE)                 // float index
#define SMEMF  (TN*XSTRIDE + TN*Pp)         // floats
#define SMEMB  (SMEMF*4)

// ---------------- device state ----------------
__device__ __nv_bfloat16 g_Wb[Bt*4*Pp*Dd];  // [b][j][p][d], j: 0=ah 1=al 2=ih 3=il
__device__ float g_cst[Bt*Pp];
__device__ float g_pi[Bt*Pp];
__device__ float g_mu[Bt*Pp*Dd];
__device__ float g_Sg[Bt*Pp*Dd];
__device__ float g_mV[Pp*Dd];
__device__ float g_wsum[Bt*Pp];
__device__ float g_wx[Bt*Pp*Dd];
__device__ float g_wxx[Bt*Pp*Dd];

// ---------------- helpers ----------------
__device__ __forceinline__ u32 splitpair(float a, float b, u32& lo) {
    __nv_bfloat162 h = __floats2bfloat162_rn(a, b);
    __nv_bfloat162 l = __floats2bfloat162_rn(a - __low2float(h), b - __high2float(h));
    lo = *(u32*)&l;
    return *(u32*)&h;
}
__device__ __forceinline__ void mmabf(float* c, const u32* a, const u32* b_) {
    asm("mma.sync.aligned.m16n8k16.row.col.f32.bf16.bf16.f32 "
        "{%0,%1,%2,%3}, {%4,%5,%6,%7}, {%8,%9}, {%0,%1,%2,%3};"
        : "+f"(c[0]), "+f"(c[1]), "+f"(c[2]), "+f"(c[3])
        : "r"(a[0]), "r"(a[1]), "r"(a[2]), "r"(a[3]), "r"(b_[0]), "r"(b_[1]));
}
__device__ __forceinline__ void bsplit(float v, float& h, float& l) {
    h = __bfloat162float(__float2bfloat16(v));
    l = v - h;
}

// ---------------- small kernels ----------------
__global__ void k_init(const float* __restrict__ m, const float* __restrict__ V_) {
    int i = blockIdx.x * blockDim.x + threadIdx.x;
    if (i < Pp*Dd) {
        float v = 0.1f * log1pf(expf(V_[i]));
        float mm = m[i];
        g_mV[i] = v + mm*mm;
        #pragma unroll
        for (int b = 0; b < Bt; b++) {
            g_mu[b*Pp*Dd + i] = mm;
            g_Sg[b*Pp*Dd + i] = v;
            g_wx[b*Pp*Dd + i] = 0.f;
            g_wxx[b*Pp*Dd + i] = 0.f;
        }
    }
    if (i < Bt*Pp) { g_pi[i] = 1.0f/Pp; g_wsum[i] = 0.f; }
}

__global__ void k_prep() {
    int b = blockIdx.x / Pp, p = blockIdx.x % Pp;
    __shared__ float red[256];
    float acc = 0.f;
    size_t wbase = (size_t)b*4*Pp*Dd;
    for (int d = threadIdx.x; d < Dd; d += 256) {
        float S  = g_Sg[(b*Pp + p)*Dd + d];
        float mu = g_mu[(b*Pp + p)*Dd + d];
        float inv = 1.0f / S;
        float a = mu * inv;
        float h, l;
        bsplit(a, h, l);
        g_Wb[wbase + (size_t)(0*Pp + p)*Dd + d] = __float2bfloat16(h);
        g_Wb[wbase + (size_t)(1*Pp + p)*Dd + d] = __float2bfloat16_rn(l);
        bsplit(inv, h, l);
        g_Wb[wbase + (size_t)(2*Pp + p)*Dd + d] = __float2bfloat16(h);
        g_Wb[wbase + (size_t)(3*Pp + p)*Dd + d] = __float2bfloat16_rn(l);
        acc += logf(S) + mu*a;
    }
    red[threadIdx.x] = acc; __syncthreads();
    for (int s = 128; s > 0; s >>= 1) {
        if (threadIdx.x < s) red[threadIdx.x] += red[threadIdx.x + s];
        __syncthreads();
    }
    if (threadIdx.x == 0)
        g_cst[b*Pp + p] = logf(g_pi[b*Pp + p]) - 0.5f * ((float)Dd * LOG2PI + red[0]);
}

__device__ __forceinline__ void load_xtile(float* xs, const float* __restrict__ dptr,
                                           int dc, int tid) {
    #pragma unroll
    for (int k = 0; k < 16; k++) {
        int lin = tid + k*256;
        int r = lin >> 5;
        int c = (lin & 31) * 4;
        float4 v = *(const float4*)(dptr + (size_t)r*Dd + dc + c);
        *(float4*)&xs[r*XSTRIDE + c] = v;
    }
}

// ---------------- main fused kernel ----------------
__global__ void __launch_bounds__(256)
k_em(const float* __restrict__ data, const float* __restrict__ mask,
     float* __restrict__ out_qq) {
    extern __shared__ float smem[];
    float* xs = smem;
    float* qs = smem + O_QS;

    const int b  = blockIdx.y;
    const int n0 = blockIdx.x * TN;
    const int tid = threadIdx.x;
    const float* dptr = data + ((size_t)b*Nn + n0) * Dd;

    // ============ E-step: mma.sync bf16 2-way split ============
    {
        const int warp = tid >> 5, lane = tid & 31;
        const int g = lane >> 2, qr = lane & 3;
        const float* x0 = dptr + (size_t)(warp*16 + g)*Dd;
        const float* x1 = x0 + 8*Dd;
        const __nv_bfloat16* wb = g_Wb + (size_t)b*4*Pp*Dd;

        float c1[2][4], c2[2][4];
        #pragma unroll
        for (int f = 0; f < 2; f++)
            #pragma unroll
            for (int k = 0; k < 4; k++) { c1[f][k] = 0.f; c2[f][k] = 0.f; }

        for (int dc = 0; dc < Dd; dc += 16) {
            const int c0 = dc + qr*2;
            float2 v00 = *(const float2*)(x0 + c0);
            float2 v01 = *(const float2*)(x0 + c0 + 8);
            float2 v10 = *(const float2*)(x1 + c0);
            float2 v11 = *(const float2*)(x1 + c0 + 8);

            u32 axh[4], axl[4], aqh[4], aql[4];
            axh[0] = splitpair(v00.x, v00.y, axl[0]);
            axh[1] = splitpair(v10.x, v10.y, axl[1]);
            axh[2] = splitpair(v01.x, v01.y, axl[2]);
            axh[3] = splitpair(v11.x, v11.y, axl[3]);
            aqh[0] = splitpair(v00.x*v00.x, v00.y*v00.y, aql[0]);
            aqh[1] = splitpair(v10.x*v10.x, v10.y*v10.y, aql[1]);
            aqh[2] = splitpair(v01.x*v01.x, v01.y*v01.y, aql[2]);
            aqh[3] = splitpair(v11.x*v11.x, v11.y*v11.y, aql[3]);

            #pragma unroll
            for (int f = 0; f < 2; f++) {
                const __nv_bfloat16* wp = wb + (size_t)(f*8 + g)*Dd + c0;
                u32 bah[2], bal[2], bih[2], bil[2];
                bah[0] = *(const u32*)(wp);              bah[1] = *(const u32*)(wp + 8);
                bal[0] = *(const u32*)(wp + Pp*Dd);      bal[1] = *(const u32*)(wp + Pp*Dd + 8);
                bih[0] = *(const u32*)(wp + 2*Pp*Dd);    bih[1] = *(const u32*)(wp + 2*Pp*Dd + 8);
                bil[0] = *(const u32*)(wp + 3*Pp*Dd);    bil[1] = *(const u32*)(wp + 3*Pp*Dd + 8);
                mmabf(c1[f], axh, bah);
                mmabf(c1[f], axh, bal);
                mmabf(c1[f], axl, bah);
                mmabf(c2[f], aqh, bih);
                mmabf(c2[f], aqh, bil);
                mmabf(c2[f], aql, bih);
            }
        }
        // write jll (minus cst) to qs: C[m][n], rows g/g+8, cols qr*2/qr*2+1 per n8 frag
        #pragma unroll
        for (int f = 0; f < 2; f++) {
            int rbase = warp*16 + g;
            int pcol = f*8 + qr*2;
            qs[(rbase    )*Pp + pcol    ] = c1[f][0] - 0.5f*c2[f][0];
            qs[(rbase    )*Pp + pcol + 1] = c1[f][1] - 0.5f*c2[f][1];
            qs[(rbase + 8)*Pp + pcol    ] = c1[f][2] - 0.5f*c2[f][2];
            qs[(rbase + 8)*Pp + pcol + 1] = c1[f][3] - 0.5f*c2[f][3];
        }
    }
    __syncthreads();

    // ============ softmax -> qq ============
    if (tid < TN) {
        int n = tid;
        float v[Pp];
        float mx = -3.4e38f;
        #pragma unroll
        for (int k = 0; k < Pp; k++) {
            v[k] = g_cst[b*Pp + k] + qs[n*Pp + k];
            mx = fmaxf(mx, v[k]);
        }
        float ssum = 0.f;
        #pragma unroll
        for (int k = 0; k < Pp; k++) { v[k] = expf(v[k] - mx); ssum += v[k]; }
        float w = mask[(size_t)b*Nn + n0 + n] / ssum;
        float* op = out_qq + ((size_t)(b*Nn + n0 + n)) * Pp;
        #pragma unroll
        for (int k = 0; k < Pp; k++) qs[n*Pp + k] = v[k] * w;
        #pragma unroll
        for (int k = 0; k < Pp; k += 4)
            *(float4*)(op + k) = make_float4(qs[n*Pp+k], qs[n*Pp+k+1], qs[n*Pp+k+2], qs[n*Pp+k+3]);
    }
    __syncthreads();

    // wsum partial
    if (tid < Pp) {
        float s = 0.f;
        for (int n = 0; n < TN; n++) s += qs[n*Pp + tid];
        atomicAdd(&g_wsum[b*Pp + tid], s);
    }
    __syncthreads();

    // ============ M-step (scalar, proven) ============
    const int q0 = (tid & 7) * 2;
    const int d0 = (tid >> 3) * 4;

    for (int dc = 0; dc < Dd; dc += DK) {
        load_xtile(xs, dptr, dc, tid);
        __syncthreads();

        float wx[2][4], wxx[2][4];
        #pragma unroll
        for (int a = 0; a < 2; a++)
            #pragma unroll
            for (int j = 0; j < 4; j++) { wx[a][j] = 0.f; wxx[a][j] = 0.f; }

        for (int n = 0; n < TN; n++) {
            float2 qv = *(const float2*)&qs[n*Pp + q0];
            float xa[4];
            *(float4*)xa = *(const float4*)&xs[n*XSTRIDE + d0];
            #pragma unroll
            for (int j = 0; j < 4; j++) {
                float x = xa[j], x2 = x*x;
                wx[0][j]  = fmaf(qv.x, x,  wx[0][j]);
                wx[1][j]  = fmaf(qv.y, x,  wx[1][j]);
                wxx[0][j] = fmaf(qv.x, x2, wxx[0][j]);
                wxx[1][j] = fmaf(qv.y, x2, wxx[1][j]);
            }
        }
        #pragma unroll
        for (int a = 0; a < 2; a++) {
            size_t base = ((size_t)(b*Pp + q0 + a))*Dd + dc + d0;
            #pragma unroll
            for (int j = 0; j < 4; j++) {
                atomicAdd(&g_wx[base + j],  wx[a][j]);
                atomicAdd(&g_wxx[base + j], wxx[a][j]);
            }
        }
        __syncthreads();
    }
}

__global__ void k_fin(const float* __restrict__ m) {
    int idx = blockIdx.x * 256 + threadIdx.x;
    int b = idx / (Pp*Dd);
    int r = idx % (Pp*Dd);
    int p = r / Dd;
    float ws = g_wsum[b*Pp + p] + 1.0f;
    float mu = (g_wx[idx] + m[r]) / ws;
    float Sg = (g_wxx[idx] + g_mV[r]) / ws - mu*mu;
    g_mu[idx] = mu;
    g_Sg[idx] = Sg;
    g_wx[idx]  = 0.f;
    g_wxx[idx] = 0.f;
}

__global__ void k_pik() {
    int b = blockIdx.x, t = threadIdx.x;
    float v = (t < Pp) ? (g_wsum[b*Pp + t] + 1.0f) : 0.f;
    float tot = v;
    #pragma unroll
    for (int o = 16; o > 0; o >>= 1) tot += __shfl_xor_sync(0xffffffffu, tot, o);
    if (t < Pp) {
        g_pi[b*Pp + t] = v / tot;
        g_wsum[b*Pp + t] = 0.f;
    }
}

__global__ void k_out(float* __restrict__ out) {
    int idx = blockIdx.x * 256 + threadIdx.x;
    out[Bt*Pp + idx] = g_mu[idx];
    out[Bt*Pp + Bt*Pp*Dd + idx] = g_Sg[idx];
    if (idx < Bt*Pp) out[idx] = g_pi[idx];
}

extern "C" void kernel_launch(void* const* d_in, const int* in_sizes, int n_in,
                              void* d_out, int out_size) {
    const float* data = (const float*)d_in[0];
    const float* mask = (const float*)d_in[1];
    const float* m    = (const float*)d_in[2];
    const float* V_   = (const float*)d_in[3];
    float* out = (float*)d_out;

    cudaFuncSetAttribute(k_em, cudaFuncAttributeMaxDynamicSharedMemorySize, SMEMB);
    const int qq_off = Bt*Pp + 2*Bt*Pp*Dd;

    k_init<<<(Pp*Dd + 255)/256, 256>>>(m, V_);
    for (int it = 0; it < ITERS; it++) {
        k_prep<<<Bt*Pp, 256>>>();
        k_em<<<dim3(NT, Bt), 256, SMEMB>>>(data, mask, out + qq_off);
        k_fin<<<(Bt*Pp*Dd)/256, 256>>>(m);
        k_pik<<<Bt, 32>>>();
    }
    k_out<<<(Bt*Pp*Dd)/256, 256>>>(out);
}

// round 14
// speedup vs baseline: 1.0817x; 1.0817x over previous
#include <cuda_runtime.h>
#include <math.h>

#define Bt 8
#define Nn 4096
#define Dd 1024
#define Pp 16
#define ITERS 3
#define TN 128
#define DK 128
#define NT (Nn/TN)
#define XSTRIDE (DK+4)
#define LOG2PI 1.8378770664093453f

// persistent state / scratch (no allocations allowed)
__device__ float g_A[Bt*Dd*Pp];     // [b][d][p] = mu * invSigma
__device__ float g_I[Bt*Dd*Pp];     // [b][d][p] = invSigma
__device__ float g_cst[Bt*Pp];
__device__ float g_pi[Bt*Pp];
__device__ float g_mu[Bt*Pp*Dd];
__device__ float g_Sg[Bt*Pp*Dd];
__device__ float g_mV[Pp*Dd];       // V + m*m
__device__ float g_wsum[Bt*Pp];
__device__ float g_red[Bt*Pp];      // partial sums of log S + mu^2/S
__device__ float g_wx[Bt*Pp*Dd];
__device__ float g_wxx[Bt*Pp*Dd];

__global__ void k_init(const float* __restrict__ m, const float* __restrict__ V_) {
    int i = blockIdx.x * blockDim.x + threadIdx.x;
    if (i < Pp*Dd) {
        float v = 0.1f * log1pf(expf(V_[i]));   // EPS * softplus(V_)
        float mm = m[i];
        g_mV[i] = v + mm*mm;
        #pragma unroll
        for (int b = 0; b < Bt; b++) {
            g_mu[b*Pp*Dd + i] = mm;
            g_Sg[b*Pp*Dd + i] = v;
            g_wx[b*Pp*Dd + i] = 0.f;
            g_wxx[b*Pp*Dd + i] = 0.f;
        }
    }
    if (i < Bt*Pp) { g_pi[i] = 1.0f/Pp; g_wsum[i] = 0.f; g_red[i] = 0.f; }
}

// one-time prep for iteration 0 (A, I, cst from the prior)
__global__ void k_prep() {
    int b = blockIdx.x / Pp, p = blockIdx.x % Pp;
    __shared__ float red[256];
    float acc = 0.f;
    for (int d = threadIdx.x; d < Dd; d += 256) {
        float S  = g_Sg[(b*Pp + p)*Dd + d];
        float mu = g_mu[(b*Pp + p)*Dd + d];
        float inv = 1.0f / S;
        g_A[(b*Dd + d)*Pp + p] = mu * inv;
        g_I[(b*Dd + d)*Pp + p] = inv;
        acc += logf(S) + mu*mu*inv;
    }
    red[threadIdx.x] = acc; __syncthreads();
    for (int s = 128; s > 0; s >>= 1) {
        if (threadIdx.x < s) red[threadIdx.x] += red[threadIdx.x + s];
        __syncthreads();
    }
    if (threadIdx.x == 0)
        g_cst[b*Pp + p] = logf(g_pi[b*Pp + p]) - 0.5f * ((float)Dd * LOG2PI + red[0]);
}

__device__ __forceinline__ void load_xtile(float* xs, const float* __restrict__ dptr,
                                           int dc, int tid) {
    #pragma unroll
    for (int k = 0; k < 16; k++) {
        int lin = tid + k*256;
        int r = lin >> 5;
        int c = (lin & 31) * 4;
        float4 v = *(const float4*)(dptr + (size_t)r*Dd + dc + c);
        *(float4*)&xs[r*XSTRIDE + c] = v;
    }
}

__global__ void __launch_bounds__(256)
k_em(const float* __restrict__ data, const float* __restrict__ mask,
     float* __restrict__ out_qq) {
    extern __shared__ float smem[];
    float* xs  = smem;                       // TN * XSTRIDE
    float* as_ = smem + TN*XSTRIDE;          // DK * Pp   (A, layout [dk][p])
    float* is_ = as_ + DK*Pp;                // DK * Pp   (invS)
    float* qs  = is_ + DK*Pp;                // TN * Pp   (jll then qq)

    const int b  = blockIdx.y;
    const int n0 = blockIdx.x * TN;
    const int tid = threadIdx.x;
    const float* dptr = data + ((size_t)b*Nn + n0) * Dd;

    // ---------------- phase 1: s1 = x.(mu*invS), s2 = x^2.invS ----------------
    // thread tile: 2 n rows x 4 p  (LDS.128 for a/i rows)
    const int p0 = (tid & 3) * 4;
    const int nb = (tid >> 2) * 2;

    float s1[2][4], s2[2][4];
    #pragma unroll
    for (int i = 0; i < 2; i++)
        #pragma unroll
        for (int k = 0; k < 4; k++) { s1[i][k] = 0.f; s2[i][k] = 0.f; }

    for (int dc = 0; dc < Dd; dc += DK) {
        load_xtile(xs, dptr, dc, tid);
        #pragma unroll
        for (int k = 0; k < 2; k++) {
            int lin = tid + k*256;           // 0..511
            int dkr = lin >> 2, c = (lin & 3) * 4;
            size_t g = ((size_t)b*Dd + dc + dkr)*Pp + c;
            *(float4*)&as_[dkr*Pp + c] = *(const float4*)&g_A[g];
            *(float4*)&is_[dkr*Pp + c] = *(const float4*)&g_I[g];
        }
        __syncthreads();

        for (int dk = 0; dk < DK; dk += 4) {
            float xr[2][4];
            *(float4*)xr[0] = *(const float4*)&xs[(nb  )*XSTRIDE + dk];
            *(float4*)xr[1] = *(const float4*)&xs[(nb+1)*XSTRIDE + dk];
            #pragma unroll
            for (int j = 0; j < 4; j++) {
                float4 av = *(const float4*)&as_[(dk+j)*Pp + p0];
                float4 iv = *(const float4*)&is_[(dk+j)*Pp + p0];
                #pragma unroll
                for (int i = 0; i < 2; i++) {
                    float x  = xr[i][j];
                    float x2 = x * x;
                    s1[i][0] = fmaf(x,  av.x, s1[i][0]);
                    s1[i][1] = fmaf(x,  av.y, s1[i][1]);
                    s1[i][2] = fmaf(x,  av.z, s1[i][2]);
                    s1[i][3] = fmaf(x,  av.w, s1[i][3]);
                    s2[i][0] = fmaf(x2, iv.x, s2[i][0]);
                    s2[i][1] = fmaf(x2, iv.y, s2[i][1]);
                    s2[i][2] = fmaf(x2, iv.z, s2[i][2]);
                    s2[i][3] = fmaf(x2, iv.w, s2[i][3]);
                }
            }
        }
        __syncthreads();
    }

    // jll into qs
    {
        float4 cv = *(const float4*)&g_cst[b*Pp + p0];
        #pragma unroll
        for (int i = 0; i < 2; i++) {
            float4 o;
            o.x = cv.x + s1[i][0] - 0.5f*s2[i][0];
            o.y = cv.y + s1[i][1] - 0.5f*s2[i][1];
            o.z = cv.z + s1[i][2] - 0.5f*s2[i][2];
            o.w = cv.w + s1[i][3] - 0.5f*s2[i][3];
            *(float4*)&qs[(nb+i)*Pp + p0] = o;
        }
    }
    __syncthreads();

    // ---------------- softmax -> qq ----------------
    if (tid < TN) {
        int n = tid;
        float v[Pp];
        float mx = -3.4e38f;
        #pragma unroll
        for (int k = 0; k < Pp; k++) { v[k] = qs[n*Pp + k]; mx = fmaxf(mx, v[k]); }
        float ssum = 0.f;
        #pragma unroll
        for (int k = 0; k < Pp; k++) { v[k] = expf(v[k] - mx); ssum += v[k]; }
        float w = mask[(size_t)b*Nn + n0 + n] / ssum;
        float* op = out_qq + ((size_t)(b*Nn + n0 + n)) * Pp;
        #pragma unroll
        for (int k = 0; k < Pp; k++) qs[n*Pp + k] = v[k] * w;
        #pragma unroll
        for (int k = 0; k < Pp; k += 4)
            *(float4*)(op + k) = make_float4(qs[n*Pp+k], qs[n*Pp+k+1], qs[n*Pp+k+2], qs[n*Pp+k+3]);
    }
    __syncthreads();

    // wsum partial
    if (tid < Pp) {
        float s = 0.f;
        for (int n = 0; n < TN; n++) s += qs[n*Pp + tid];
        atomicAdd(&g_wsum[b*Pp + tid], s);
    }
    __syncthreads();

    // ---------------- phase 2: wx += qq^T x, wxx += qq^T x^2 ----------------
    // thread tile: 4 p x 2 d  (q as LDS.128, x^2 amortized over 4 p)
    const int q0 = (tid & 3) * 4;
    const int d0 = (tid >> 2) * 2;

    for (int dc = 0; dc < Dd; dc += DK) {
        load_xtile(xs, dptr, dc, tid);
        __syncthreads();

        float wx[4][2], wxx[4][2];
        #pragma unroll
        for (int a = 0; a < 4; a++)
            #pragma unroll
            for (int j = 0; j < 2; j++) { wx[a][j] = 0.f; wxx[a][j] = 0.f; }

        #pragma unroll 2
        for (int n = 0; n < TN; n++) {
            float4 qv = *(const float4*)&qs[n*Pp + q0];
            float2 xv = *(const float2*)&xs[n*XSTRIDE + d0];
            float x2a = xv.x * xv.x;
            float x2b = xv.y * xv.y;
            wx[0][0]  = fmaf(qv.x, xv.x, wx[0][0]);   wx[0][1]  = fmaf(qv.x, xv.y, wx[0][1]);
            wx[1][0]  = fmaf(qv.y, xv.x, wx[1][0]);   wx[1][1]  = fmaf(qv.y, xv.y, wx[1][1]);
            wx[2][0]  = fmaf(qv.z, xv.x, wx[2][0]);   wx[2][1]  = fmaf(qv.z, xv.y, wx[2][1]);
            wx[3][0]  = fmaf(qv.w, xv.x, wx[3][0]);   wx[3][1]  = fmaf(qv.w, xv.y, wx[3][1]);
            wxx[0][0] = fmaf(qv.x, x2a,  wxx[0][0]);  wxx[0][1] = fmaf(qv.x, x2b,  wxx[0][1]);
            wxx[1][0] = fmaf(qv.y, x2a,  wxx[1][0]);  wxx[1][1] = fmaf(qv.y, x2b,  wxx[1][1]);
            wxx[2][0] = fmaf(qv.z, x2a,  wxx[2][0]);  wxx[2][1] = fmaf(qv.z, x2b,  wxx[2][1]);
            wxx[3][0] = fmaf(qv.w, x2a,  wxx[3][0]);  wxx[3][1] = fmaf(qv.w, x2b,  wxx[3][1]);
        }
        #pragma unroll
        for (int a = 0; a < 4; a++) {
            size_t base = ((size_t)(b*Pp + q0 + a))*Dd + dc + d0;
            atomicAdd(&g_wx[base],      wx[a][0]);
            atomicAdd(&g_wx[base + 1],  wx[a][1]);
            atomicAdd(&g_wxx[base],     wxx[a][0]);
            atomicAdd(&g_wxx[base + 1], wxx[a][1]);
        }
        __syncthreads();
    }
}

// fused finalize: mu/Sigma update + next-iter A/I + log-det partial reduction
__global__ void k_finp(const float* __restrict__ m) {
    __shared__ float red[256];
    int idx = blockIdx.x * 256 + threadIdx.x;    // < Bt*Pp*Dd, block = one (b,p,256d)
    int b = idx / (Pp*Dd);
    int r = idx % (Pp*Dd);
    int p = r / Dd;
    int d = r % Dd;
    float ws = g_wsum[b*Pp + p] + 1.0f;          // tau = 1
    float mu = (g_wx[idx] + m[r]) / ws;
    float Sg = (g_wxx[idx] + g_mV[r]) / ws - mu*mu;
    g_mu[idx] = mu;
    g_Sg[idx] = Sg;
    g_wx[idx]  = 0.f;
    g_wxx[idx] = 0.f;
    float inv = 1.0f / Sg;
    float a = mu * inv;
    g_A[(b*Dd + d)*Pp + p] = a;
    g_I[(b*Dd + d)*Pp + p] = inv;
    float acc = logf(Sg) + mu*a;
    red[threadIdx.x] = acc; __syncthreads();
    for (int s = 128; s > 0; s >>= 1) {
        if (threadIdx.x < s) red[threadIdx.x] += red[threadIdx.x + s];
        __syncthreads();
    }
    if (threadIdx.x == 0) atomicAdd(&g_red[b*Pp + p], red[0]);
}

// pi update + cst finalize + state reset
__global__ void k_pik() {
    int b = blockIdx.x, t = threadIdx.x;         // 32 threads
    float v = (t < Pp) ? (g_wsum[b*Pp + t] + 1.0f) : 0.f;
    float tot = v;
    #pragma unroll
    for (int o = 16; o > 0; o >>= 1) tot += __shfl_xor_sync(0xffffffffu, tot, o);
    if (t < Pp) {
        float pi = v / tot;
        g_pi[b*Pp + t] = pi;
        g_cst[b*Pp + t] = logf(pi) - 0.5f * ((float)Dd * LOG2PI + g_red[b*Pp + t]);
        g_wsum[b*Pp + t] = 0.f;
        g_red[b*Pp + t]  = 0.f;
    }
}

__global__ void k_out(float* __restrict__ out) {
    int idx = blockIdx.x * 256 + threadIdx.x;    // < Bt*Pp*Dd
    out[Bt*Pp + idx] = g_mu[idx];
    out[Bt*Pp + Bt*Pp*Dd + idx] = g_Sg[idx];
    if (idx < Bt*Pp) out[idx] = g_pi[idx];
}

extern "C" void kernel_launch(void* const* d_in, const int* in_sizes, int n_in,
                              void* d_out, int out_size) {
    const float* data = (const float*)d_in[0];
    const float* mask = (const float*)d_in[1];
    const float* m    = (const float*)d_in[2];
    const float* V_   = (const float*)d_in[3];
    float* out = (float*)d_out;

    const int smem_bytes = (TN*XSTRIDE + 2*DK*Pp + TN*Pp) * (int)sizeof(float); // 92160
    cudaFuncSetAttribute(k_em, cudaFuncAttributeMaxDynamicSharedMemorySize, smem_bytes);

    const int qq_off = Bt*Pp + 2*Bt*Pp*Dd;       // 262272

    k_init<<<(Pp*Dd + 255)/256, 256>>>(m, V_);
    k_prep<<<Bt*Pp, 256>>>();                    // iteration-0 A/I/cst
    for (int it = 0; it < ITERS; it++) {
        k_em<<<dim3(NT, Bt), 256, smem_bytes>>>(data, mask, out + qq_off);
        k_finp<<<(Bt*Pp*Dd)/256, 256>>>(m);
        k_pik<<<Bt, 32>>>();
    }
    k_out<<<(Bt*Pp*Dd)/256, 256>>>(out);
}

// round 15
// speedup vs baseline: 1.1299x; 1.0446x over previous
#include <cuda_runtime.h>
#include <math.h>

#define Bt 8
#define Nn 4096
#define Dd 1024
#define Pp 16
#define ITERS 3
#define TN 128
#define DK 128
#define NT (Nn/TN)
#define XSTRIDE (DK+4)
#define LOG2PI 1.8378770664093453f

// persistent state / scratch (no allocations allowed)
__device__ float g_A[Bt*Dd*Pp];     // [b][d][p] = mu * invSigma
__device__ float g_I[Bt*Dd*Pp];     // [b][d][p] = invSigma
__device__ float g_cst[Bt*Pp];
__device__ float g_pi[Bt*Pp];
__device__ float g_mu[Bt*Pp*Dd];
__device__ float g_Sg[Bt*Pp*Dd];
__device__ float g_mV[Pp*Dd];       // V + m*m
__device__ float g_wsum[Bt*Pp];
__device__ float g_red[Bt*Pp];      // partial sums of log S + mu^2/S
__device__ float g_wx[Bt*Pp*Dd];
__device__ float g_wxx[Bt*Pp*Dd];

__global__ void k_init(const float* __restrict__ m, const float* __restrict__ V_) {
    int i = blockIdx.x * blockDim.x + threadIdx.x;
    if (i < Pp*Dd) {
        float v = 0.1f * log1pf(expf(V_[i]));   // EPS * softplus(V_)
        float mm = m[i];
        g_mV[i] = v + mm*mm;
        #pragma unroll
        for (int b = 0; b < Bt; b++) {
            g_mu[b*Pp*Dd + i] = mm;
            g_Sg[b*Pp*Dd + i] = v;
            g_wx[b*Pp*Dd + i] = 0.f;
            g_wxx[b*Pp*Dd + i] = 0.f;
        }
    }
    if (i < Bt*Pp) { g_pi[i] = 1.0f/Pp; g_wsum[i] = 0.f; g_red[i] = 0.f; }
}

// one-time prep for iteration 0 (A, I, cst from the prior)
__global__ void k_prep() {
    int b = blockIdx.x / Pp, p = blockIdx.x % Pp;
    __shared__ float red[256];
    float acc = 0.f;
    for (int d = threadIdx.x; d < Dd; d += 256) {
        float S  = g_Sg[(b*Pp + p)*Dd + d];
        float mu = g_mu[(b*Pp + p)*Dd + d];
        float inv = 1.0f / S;
        g_A[(b*Dd + d)*Pp + p] = mu * inv;
        g_I[(b*Dd + d)*Pp + p] = inv;
        acc += logf(S) + mu*mu*inv;
    }
    red[threadIdx.x] = acc; __syncthreads();
    for (int s = 128; s > 0; s >>= 1) {
        if (threadIdx.x < s) red[threadIdx.x] += red[threadIdx.x + s];
        __syncthreads();
    }
    if (threadIdx.x == 0)
        g_cst[b*Pp + p] = logf(g_pi[b*Pp + p]) - 0.5f * ((float)Dd * LOG2PI + red[0]);
}

__device__ __forceinline__ void load_xtile(float* xs, const float* __restrict__ dptr,
                                           int dc, int tid) {
    #pragma unroll
    for (int k = 0; k < 16; k++) {
        int lin = tid + k*256;
        int r = lin >> 5;
        int c = (lin & 31) * 4;
        float4 v = *(const float4*)(dptr + (size_t)r*Dd + dc + c);
        *(float4*)&xs[r*XSTRIDE + c] = v;
    }
}

__global__ void __launch_bounds__(256)
k_em(const float* __restrict__ data, const float* __restrict__ mask,
     float* __restrict__ out_qq) {
    extern __shared__ float smem[];
    float* xs  = smem;                       // TN * XSTRIDE
    float* as_ = smem + TN*XSTRIDE;          // DK * Pp   (A, layout [dk][p])
    float* is_ = as_ + DK*Pp;                // DK * Pp   (invS)
    float* qs  = is_ + DK*Pp;                // TN * Pp   (jll then qq)

    const int b  = blockIdx.y;
    const int n0 = blockIdx.x * TN;
    const int tid = threadIdx.x;
    const float* dptr = data + ((size_t)b*Nn + n0) * Dd;

    // ---------------- phase 1: s1 = x.(mu*invS), s2 = x^2.invS ----------------
    // thread tile: 4 n rows x 2 p (proven fastest, R0)
    const int pp = tid & 7, p0 = pp * 2;
    const int nb = (tid >> 3) * 4;

    float s1[4][2], s2[4][2];
    #pragma unroll
    for (int i = 0; i < 4; i++) { s1[i][0]=s1[i][1]=s2[i][0]=s2[i][1]=0.f; }

    for (int dc = 0; dc < Dd; dc += DK) {
        load_xtile(xs, dptr, dc, tid);
        #pragma unroll
        for (int k = 0; k < 2; k++) {
            int lin = tid + k*256;           // 0..511
            int dkr = lin >> 2, c = (lin & 3) * 4;
            size_t g = ((size_t)b*Dd + dc + dkr)*Pp + c;
            *(float4*)&as_[dkr*Pp + c] = *(const float4*)&g_A[g];
            *(float4*)&is_[dkr*Pp + c] = *(const float4*)&g_I[g];
        }
        __syncthreads();

        for (int dk = 0; dk < DK; dk += 4) {
            float xr[4][4];
            #pragma unroll
            for (int i = 0; i < 4; i++)
                *(float4*)xr[i] = *(const float4*)&xs[(nb+i)*XSTRIDE + dk];
            #pragma unroll
            for (int j = 0; j < 4; j++) {
                float2 av = *(const float2*)&as_[(dk+j)*Pp + p0];
                float2 iv = *(const float2*)&is_[(dk+j)*Pp + p0];
                #pragma unroll
                for (int i = 0; i < 4; i++) {
                    float x  = xr[i][j];
                    float x2 = x * x;
                    s1[i][0] = fmaf(x,  av.x, s1[i][0]);
                    s1[i][1] = fmaf(x,  av.y, s1[i][1]);
                    s2[i][0] = fmaf(x2, iv.x, s2[i][0]);
                    s2[i][1] = fmaf(x2, iv.y, s2[i][1]);
                }
            }
        }
        __syncthreads();
    }

    // jll into qs
    {
        float c0 = g_cst[b*Pp + p0];
        float c1 = g_cst[b*Pp + p0 + 1];
        #pragma unroll
        for (int i = 0; i < 4; i++) {
            qs[(nb+i)*Pp + p0    ] = c0 + s1[i][0] - 0.5f*s2[i][0];
            qs[(nb+i)*Pp + p0 + 1] = c1 + s1[i][1] - 0.5f*s2[i][1];
        }
    }
    __syncthreads();

    // ---------------- softmax -> qq ----------------
    if (tid < TN) {
        int n = tid;
        float v[Pp];
        float mx = -3.4e38f;
        #pragma unroll
        for (int k = 0; k < Pp; k++) { v[k] = qs[n*Pp + k]; mx = fmaxf(mx, v[k]); }
        float ssum = 0.f;
        #pragma unroll
        for (int k = 0; k < Pp; k++) { v[k] = expf(v[k] - mx); ssum += v[k]; }
        float w = mask[(size_t)b*Nn + n0 + n] / ssum;
        float* op = out_qq + ((size_t)(b*Nn + n0 + n)) * Pp;
        #pragma unroll
        for (int k = 0; k < Pp; k++) qs[n*Pp + k] = v[k] * w;
        #pragma unroll
        for (int k = 0; k < Pp; k += 4)
            *(float4*)(op + k) = make_float4(qs[n*Pp+k], qs[n*Pp+k+1], qs[n*Pp+k+2], qs[n*Pp+k+3]);
    }
    __syncthreads();

    // wsum partial
    if (tid < Pp) {
        float s = 0.f;
        for (int n = 0; n < TN; n++) s += qs[n*Pp + tid];
        atomicAdd(&g_wsum[b*Pp + tid], s);
    }
    __syncthreads();

    // ---------------- phase 2: wx += qq^T x, wxx += qq^T x^2 ----------------
    // thread tile: 2 p x 4 d (proven fastest, R0)
    const int q0 = (tid & 7) * 2;
    const int d0 = (tid >> 3) * 4;

    for (int dc = 0; dc < Dd; dc += DK) {
        load_xtile(xs, dptr, dc, tid);
        __syncthreads();

        float wx[2][4], wxx[2][4];
        #pragma unroll
        for (int a = 0; a < 2; a++)
            #pragma unroll
            for (int j = 0; j < 4; j++) { wx[a][j] = 0.f; wxx[a][j] = 0.f; }

        for (int n = 0; n < TN; n++) {
            float2 qv = *(const float2*)&qs[n*Pp + q0];
            float xa[4];
            *(float4*)xa = *(const float4*)&xs[n*XSTRIDE + d0];
            #pragma unroll
            for (int j = 0; j < 4; j++) {
                float x = xa[j], x2 = x*x;
                wx[0][j]  = fmaf(qv.x, x,  wx[0][j]);
                wx[1][j]  = fmaf(qv.y, x,  wx[1][j]);
                wxx[0][j] = fmaf(qv.x, x2, wxx[0][j]);
                wxx[1][j] = fmaf(qv.y, x2, wxx[1][j]);
            }
        }
        #pragma unroll
        for (int a = 0; a < 2; a++) {
            size_t base = ((size_t)(b*Pp + q0 + a))*Dd + dc + d0;
            #pragma unroll
            for (int j = 0; j < 4; j++) {
                atomicAdd(&g_wx[base + j],  wx[a][j]);
                atomicAdd(&g_wxx[base + j], wxx[a][j]);
            }
        }
        __syncthreads();
    }
}

// fused finalize: mu/Sigma update + next-iter A/I + log-det partial reduction
__global__ void k_finp(const float* __restrict__ m) {
    __shared__ float red[256];
    int idx = blockIdx.x * 256 + threadIdx.x;    // < Bt*Pp*Dd, block = one (b,p,256d)
    int b = idx / (Pp*Dd);
    int r = idx % (Pp*Dd);
    int p = r / Dd;
    int d = r % Dd;
    float ws = g_wsum[b*Pp + p] + 1.0f;          // tau = 1
    float mu = (g_wx[idx] + m[r]) / ws;
    float Sg = (g_wxx[idx] + g_mV[r]) / ws - mu*mu;
    g_mu[idx] = mu;
    g_Sg[idx] = Sg;
    g_wx[idx]  = 0.f;
    g_wxx[idx] = 0.f;
    float inv = 1.0f / Sg;
    float a = mu * inv;
    g_A[(b*Dd + d)*Pp + p] = a;
    g_I[(b*Dd + d)*Pp + p] = inv;
    float acc = logf(Sg) + mu*a;
    red[threadIdx.x] = acc; __syncthreads();
    for (int s = 128; s > 0; s >>= 1) {
        if (threadIdx.x < s) red[threadIdx.x] += red[threadIdx.x + s];
        __syncthreads();
    }
    if (threadIdx.x == 0) atomicAdd(&g_red[b*Pp + p], red[0]);
}

// pi update + cst finalize + state reset
__global__ void k_pik() {
    int b = blockIdx.x, t = threadIdx.x;         // 32 threads
    float v = (t < Pp) ? (g_wsum[b*Pp + t] + 1.0f) : 0.f;
    float tot = v;
    #pragma unroll
    for (int o = 16; o > 0; o >>= 1) tot += __shfl_xor_sync(0xffffffffu, tot, o);
    if (t < Pp) {
        float pi = v / tot;
        g_pi[b*Pp + t] = pi;
        g_cst[b*Pp + t] = logf(pi) - 0.5f * ((float)Dd * LOG2PI + g_red[b*Pp + t]);
        g_wsum[b*Pp + t] = 0.f;
        g_red[b*Pp + t]  = 0.f;
    }
}

__global__ void k_out(float* __restrict__ out) {
    int idx = blockIdx.x * 256 + threadIdx.x;    // < Bt*Pp*Dd
    out[Bt*Pp + idx] = g_mu[idx];
    out[Bt*Pp + Bt*Pp*Dd + idx] = g_Sg[idx];
    if (idx < Bt*Pp) out[idx] = g_pi[idx];
}

extern "C" void kernel_launch(void* const* d_in, const int* in_sizes, int n_in,
                              void* d_out, int out_size) {
    const float* data = (const float*)d_in[0];
    const float* mask = (const float*)d_in[1];
    const float* m    = (const float*)d_in[2];
    const float* V_   = (const float*)d_in[3];
    float* out = (float*)d_out;

    const int smem_bytes = (TN*XSTRIDE + 2*DK*Pp + TN*Pp) * (int)sizeof(float); // 92160
    cudaFuncSetAttribute(k_em, cudaFuncAttributeMaxDynamicSharedMemorySize, smem_bytes);

    const int qq_off = Bt*Pp + 2*Bt*Pp*Dd;       // 262272

    k_init<<<(Pp*Dd + 255)/256, 256>>>(m, V_);
    k_prep<<<Bt*Pp, 256>>>();                    // iteration-0 A/I/cst
    for (int it = 0; it < ITERS; it++) {
        k_em<<<dim3(NT, Bt), 256, smem_bytes>>>(data, mask, out + qq_off);
        k_finp<<<(Bt*Pp*Dd)/256, 256>>>(m);
        k_pik<<<Bt, 32>>>();
    }
    k_out<<<(Bt*Pp*Dd)/256, 256>>>(out);
}